// round 16
// baseline (speedup 1.0000x reference)
#include <cuda_runtime.h>
#include <cuda_bf16.h>
#include <math.h>
#include <stdint.h>

#define N_ROWS 32768
#define DIM    256
#define KCODES 8192

#define BM      128
#define BNH     128                  // k-tile width processed per stage
#define KQW     2048                 // codes per job (k-quarter)
#define NJOBS   ((N_ROWS / BM) * (KCODES / KQW))   // 256 * 4 = 1024
#define P1GRID  152                  // persistent CTAs (GB300: 152 SMs)
#define CAND_MAX 64
#define MARGIN  0.125f

// ---- scratch (device globals; no runtime allocation) ----
__device__ float    g_xnorm[N_ROWS];
__device__ float    g_enorm[KCODES];
__device__ float    g_embT[KCODES * DIM];               // [K][D] fp32 rescore/gather
__device__ __nv_bfloat16 g_Eh[KCODES * DIM];            // [K][D] bf16
__device__ __nv_bfloat16 g_Xh[(size_t)N_ROWS * DIM];    // [N][D] bf16
__device__ int      g_cand[(size_t)N_ROWS * CAND_MAX];
__device__ int      g_candCnt[N_ROWS];
__device__ unsigned g_rowKey[N_ROWS];                   // global running-min key
__device__ int      g_jobCtr;
__device__ double   g_partial[N_ROWS];

// =========================== helpers ===================================
__device__ __forceinline__ uint32_t s2u(const void* p) {
    uint32_t a;
    asm("{ .reg .u64 t; cvta.to.shared.u64 t, %1; cvt.u32.u64 %0, t; }" : "=r"(a) : "l"(p));
    return a;
}
__device__ __forceinline__ unsigned fenc(float f) {
    unsigned b = __float_as_uint(f);
    return (b & 0x80000000u) ? ~b : (b | 0x80000000u);
}
__device__ __forceinline__ float fdec(unsigned u) {
    return (u & 0x80000000u) ? __uint_as_float(u & 0x7FFFFFFFu) : __uint_as_float(~u);
}
__device__ __forceinline__ void ldsm4(uint32_t* d, uint32_t addr) {
    asm volatile("ldmatrix.sync.aligned.m8n8.x4.shared.b16 {%0,%1,%2,%3}, [%4];"
        : "=r"(d[0]), "=r"(d[1]), "=r"(d[2]), "=r"(d[3]) : "r"(addr));
}
__device__ __forceinline__ void mma_bf16(float* c, const uint32_t* a, const uint32_t* b) {
    asm volatile("mma.sync.aligned.m16n8k16.row.col.f32.bf16.bf16.f32 "
        "{%0,%1,%2,%3}, {%4,%5,%6,%7}, {%8,%9}, {%0,%1,%2,%3};"
        : "+f"(c[0]), "+f"(c[1]), "+f"(c[2]), "+f"(c[3])
        : "r"(a[0]), "r"(a[1]), "r"(a[2]), "r"(a[3]), "r"(b[0]), "r"(b[1]));
}
__device__ __forceinline__ void cpa16(uint32_t dst, const void* src) {
    asm volatile("cp.async.cg.shared.global [%0], [%1], 16;" :: "r"(dst), "l"(src));
}
#define CP_COMMIT() asm volatile("cp.async.commit_group;" ::: "memory")
#define CP_WAIT0()  asm volatile("cp.async.wait_group 0;" ::: "memory")
#define HBAR(h)     asm volatile("bar.sync %0, %1;" :: "r"(1 + (h)), "r"(256) : "memory")

// ======================= fused prep kernel ================================
// [0,32) enorm | [32,2080) prepE | [2080,6176) prepX | [6176,6304) init
#define PREP_ENORM 32
#define PREP_E     2048
#define PREP_X     4096
#define PREP_Z     128
#define PREP_GRID  (PREP_ENORM + PREP_E + PREP_X + PREP_Z)

__global__ __launch_bounds__(256) void prep_kernel(const float* __restrict__ X,
                                                   const float* __restrict__ E) {
    int b = blockIdx.x;
    if (b < PREP_ENORM) {
        int k = b * 256 + threadIdx.x;
        float s = 0.0f;
        #pragma unroll 8
        for (int d = 0; d < DIM; d++) { float v = E[(size_t)d * KCODES + k]; s += v * v; }
        g_enorm[k] = s;
    } else if (b < PREP_ENORM + PREP_E) {
        __shared__ float tile[32][33];
        int idx = b - PREP_ENORM;
        int kBase = (idx & 255) * 32, dBase = (idx >> 8) * 32;
        int tx = threadIdx.x & 31, ty = threadIdx.x >> 5;
        #pragma unroll
        for (int i = 0; i < 32; i += 8)
            tile[ty + i][tx] = E[(size_t)(dBase + ty + i) * KCODES + kBase + tx];
        __syncthreads();
        #pragma unroll
        for (int i = 0; i < 32; i += 8) {
            float v = tile[tx][ty + i];
            size_t o = (size_t)(kBase + ty + i) * DIM + dBase + tx;
            g_embT[o] = v;
            g_Eh[o] = __float2bfloat16(v);
        }
    } else if (b < PREP_ENORM + PREP_E + PREP_X) {
        int idx = b - (PREP_ENORM + PREP_E);
        int gwarp = (idx * 256 + threadIdx.x) >> 5;
        int lane = threadIdx.x & 31;
        const float* xr = X + (size_t)gwarp * DIM;
        float4 a = *(const float4*)&xr[lane * 8];
        float4 bb = *(const float4*)&xr[lane * 8 + 4];
        float s = a.x * a.x + a.y * a.y + a.z * a.z + a.w * a.w;
        s += bb.x * bb.x + bb.y * bb.y + bb.z * bb.z + bb.w * bb.w;
        #pragma unroll
        for (int off = 16; off > 0; off >>= 1) s += __shfl_xor_sync(0xFFFFFFFFu, s, off);
        if (lane == 0) g_xnorm[gwarp] = s;
        __nv_bfloat162 p0 = make_bfloat162(__float2bfloat16(a.x), __float2bfloat16(a.y));
        __nv_bfloat162 p1 = make_bfloat162(__float2bfloat16(a.z), __float2bfloat16(a.w));
        __nv_bfloat162 p2 = make_bfloat162(__float2bfloat16(bb.x), __float2bfloat16(bb.y));
        __nv_bfloat162 p3 = make_bfloat162(__float2bfloat16(bb.z), __float2bfloat16(bb.w));
        uint4 v = make_uint4(*(uint32_t*)&p0, *(uint32_t*)&p1, *(uint32_t*)&p2, *(uint32_t*)&p3);
        *(uint4*)&g_Xh[(size_t)gwarp * DIM + lane * 8] = v;
    } else {
        // ---- per-launch init (graph-replay safe) ----
        int idx = b - (PREP_ENORM + PREP_E + PREP_X);
        int i = idx * 256 + threadIdx.x;
        g_candCnt[i] = 0;
        g_rowKey[i] = 0xFFFFFFFFu;
        if (i == 0) g_jobCtr = 0;
    }
}

// ==== phase 1: persistent CTAs, job stealing, two desynced halves =========
// smem: A 64KB | B[half][buf] 4x32KB
#define SMEM_BBASE 65536
#define BUFOFF(h, b) (SMEM_BBASE + ((h) * 2 + (b)) * 32768)
#define SMEM_P1    196608

__global__ __launch_bounds__(512, 1) void phase1_kernel() {
    extern __shared__ char smem[];
    __shared__ int s_job;
    uint32_t sb = s2u(smem);

    int tid = threadIdx.x, lane = tid & 31, wid = tid >> 5;
    int half = wid >> 3;
    int wh = wid & 7, wm = wh >> 1, wn = wh & 1;   // 4x2 grid, warp tile 32x64
    int g = lane >> 2, q = lane & 3;
    int htid = tid & 255;

    int rA = wm * 32 + (lane & 7) + ((lane >> 3) & 1) * 8;
    int caBit = lane >> 4;
    int rB = wn * 64 + (lane & 7) + ((lane >> 4) & 1) * 8;
    int cbBit = (lane >> 3) & 1;
    uint32_t aRowBase = sb + rA * 512;

    int cur_rt = -1;
    for (;;) {
        __syncthreads();
        if (tid == 0) s_job = atomicAdd(&g_jobCtr, 1);
        __syncthreads();
        int job = s_job;
        if (job >= NJOBS) break;
        int rt = job >> 2, kq = job & 3;
        int rowBase = rt * BM;
        int khalf = kq * KQW + half * (KQW / 2);

        // A tile load (64KB, all 512 threads) only when row-tile changes
        if (rt != cur_rt) {
            const char* srcA = (const char*)g_Xh + (size_t)rowBase * 512;
            #pragma unroll
            for (int i = 0; i < 8; i++) {
                int lin = tid + i * 512;
                int r = lin >> 5, c = lin & 31;
                int gs = (c & ~7) | ((c ^ r) & 7);
                cpa16(sb + r * 512 + gs * 16, srcA + (size_t)r * 512 + c * 16);
            }
        }
        // stage-0 B chunk for this half (tile 0, dchunk 0)
        {
            const char* srcB = (const char*)g_Eh + (size_t)khalf * 512;
            uint32_t dstB = sb + BUFOFF(half, 0);
            #pragma unroll
            for (int i = 0; i < 8; i++) {
                int lin = htid + i * 256;
                int r = lin >> 4, c = lin & 15;
                int gs = (c & ~7) | ((c ^ r) & 7);
                cpa16(dstB + r * 256 + gs * 16, srcB + (size_t)r * 512 + c * 16);
            }
        }
        CP_COMMIT();
        CP_WAIT0();
        __syncthreads();          // A visible to both halves
        cur_rt = rt;

        float acc[2][8][4];
        int buf = 0;
        #pragma unroll 1
        for (int s = 0; s < 16; s++) {          // 8 ktiles x 2 dchunks
            int t = s >> 1, dc = s & 1;
            int kbase = khalf + t * BNH;

            if (s + 1 < 16) {
                int t2 = (s + 1) >> 1, dc2 = (s + 1) & 1;
                const char* srcB = (const char*)g_Eh
                    + (size_t)(khalf + t2 * BNH) * 512 + dc2 * 256;
                uint32_t dstB = sb + BUFOFF(half, buf ^ 1);
                #pragma unroll
                for (int i = 0; i < 8; i++) {
                    int lin = htid + i * 256;
                    int r = lin >> 4, c = lin & 15;
                    int gs = (c & ~7) | ((c ^ r) & 7);
                    cpa16(dstB + r * 256 + gs * 16, srcB + (size_t)r * 512 + c * 16);
                }
                CP_COMMIT();
            }

            if (dc == 0) {
                #pragma unroll
                for (int mt = 0; mt < 2; mt++)
                    #pragma unroll
                    for (int nt = 0; nt < 8; nt++)
                        #pragma unroll
                        for (int e = 0; e < 4; e++) acc[mt][nt][e] = 0.0f;
            }
            float en[8][2];
            unsigned key[2][2];
            if (dc == 1) {
                #pragma unroll
                for (int nt = 0; nt < 8; nt++)
                    #pragma unroll
                    for (int e = 0; e < 2; e++)
                        en[nt][e] = __ldg(&g_enorm[kbase + wn * 64 + nt * 8 + q * 2 + e]);
                #pragma unroll
                for (int mt = 0; mt < 2; mt++)
                    #pragma unroll
                    for (int h2 = 0; h2 < 2; h2++)
                        key[mt][h2] = __ldcg(&g_rowKey[rowBase + wm * 32 + mt * 16 + g + h2 * 8]);
            }

            uint32_t bChunk = sb + BUFOFF(half, buf) + rB * 256;
            #pragma unroll
            for (int ks = 0; ks < 8; ks++) {
                uint32_t af0[4], af1[4], bf[4][4];
                int ksg = dc * 8 + ks;
                int cA = ksg * 2 + caBit;
                int gsA = (cA & ~7) | ((cA ^ rA) & 7);
                uint32_t aAddr = aRowBase + gsA * 16;
                ldsm4(af0, aAddr);
                ldsm4(af1, aAddr + 16 * 512);
                int cB = ks * 2 + cbBit;
                int gsB = (cB & ~7) | ((cB ^ rB) & 7);
                uint32_t bAddr = bChunk + gsB * 16;
                ldsm4(bf[0], bAddr);
                ldsm4(bf[1], bAddr + 16 * 256);
                ldsm4(bf[2], bAddr + 32 * 256);
                ldsm4(bf[3], bAddr + 48 * 256);
                #pragma unroll
                for (int nt = 0; nt < 8; nt++) {
                    mma_bf16(acc[0][nt], af0, bf[nt >> 1] + 2 * (nt & 1));
                    mma_bf16(acc[1][nt], af1, bf[nt >> 1] + 2 * (nt & 1));
                }
            }

            if (dc == 1) {
                #pragma unroll
                for (int mt = 0; mt < 2; mt++) {
                    #pragma unroll
                    for (int h2 = 0; h2 < 2; h2++) {
                        int rl = wm * 32 + mt * 16 + g + h2 * 8;
                        int row = rowBase + rl;
                        unsigned ck = key[mt][h2];
                        if (ck == 0xFFFFFFFFu) {
                            // unseeded row: min-prepass (sentinel decodes to NaN)
                            float tm0 = INFINITY;
                            #pragma unroll
                            for (int nt = 0; nt < 8; nt++)
                                #pragma unroll
                                for (int e = 0; e < 2; e++)
                                    tm0 = fminf(tm0, fmaf(-2.0f, acc[mt][nt][h2 * 2 + e], en[nt][e]));
                            unsigned mk = fenc(tm0);
                            unsigned old = atomicMin(&g_rowKey[row], mk);
                            ck = old < mk ? old : mk;
                        }
                        float thr = fdec(ck) + MARGIN;
                        float tm = INFINITY;
                        #pragma unroll
                        for (int nt = 0; nt < 8; nt++)
                            #pragma unroll
                            for (int e = 0; e < 2; e++) {
                                float d = fmaf(-2.0f, acc[mt][nt][h2 * 2 + e], en[nt][e]);
                                tm = fminf(tm, d);
                                if (d < thr) {
                                    int pos = atomicAdd(&g_candCnt[row], 1);
                                    if (pos < CAND_MAX)
                                        g_cand[(size_t)row * CAND_MAX + pos] =
                                            kbase + wn * 64 + nt * 8 + q * 2 + e;
                                }
                            }
                        if (fenc(tm) < ck) atomicMin(&g_rowKey[row], fenc(tm));
                    }
                }
            }

            CP_WAIT0();
            HBAR(half);
            buf ^= 1;
        }
    }
}

// ===== phase 2: exact fp32 rescore + fused gather/output/loss-partial ======
__global__ __launch_bounds__(256) void rescore_gather_kernel(const float* __restrict__ X,
                                                             float* __restrict__ out) {
    int gw = (blockIdx.x * blockDim.x + threadIdx.x) >> 5;   // one warp per row
    int lane = threadIdx.x & 31;
    const float* xr = X + (size_t)gw * DIM;
    float xn = g_xnorm[gw];
    int cnt = g_candCnt[gw];
    float bv = INFINITY;
    int   bi = 0x7FFFFFFF;

    if (cnt <= CAND_MAX) {
        float4 xa = *(const float4*)&xr[lane * 8];
        float4 xb = *(const float4*)&xr[lane * 8 + 4];
        for (int ci = 0; ci < cnt; ci++) {
            int k = g_cand[(size_t)gw * CAND_MAX + ci];
            const float* er = g_embT + (size_t)k * DIM;
            float4 ea = *(const float4*)&er[lane * 8];
            float4 eb = *(const float4*)&er[lane * 8 + 4];
            float d = xa.x * ea.x + xa.y * ea.y + xa.z * ea.z + xa.w * ea.w
                    + xb.x * eb.x + xb.y * eb.y + xb.z * eb.z + xb.w * eb.w;
            #pragma unroll
            for (int off = 16; off > 0; off >>= 1) d += __shfl_xor_sync(0xFFFFFFFFu, d, off);
            float dist = fmaf(-2.0f, d, xn) + g_enorm[k];
            if (dist < bv || (dist == bv && k < bi)) { bv = dist; bi = k; }
        }
    } else {
        // rare overflow: full exact scan
        for (int k = lane; k < KCODES; k += 32) {
            const float* er = g_embT + (size_t)k * DIM;
            float d = 0.0f;
            #pragma unroll 8
            for (int j = 0; j < DIM; j += 4) {
                float4 e4 = *(const float4*)&er[j];
                float4 x4 = *(const float4*)&xr[j];
                d += x4.x * e4.x + x4.y * e4.y + x4.z * e4.z + x4.w * e4.w;
            }
            float dist = fmaf(-2.0f, d, xn) + g_enorm[k];
            if (dist < bv || (dist == bv && k < bi)) { bv = dist; bi = k; }
        }
    }
    #pragma unroll
    for (int off = 16; off > 0; off >>= 1) {
        float ov = __shfl_xor_sync(0xFFFFFFFFu, bv, off);
        int   oi = __shfl_xor_sync(0xFFFFFFFFu, bi, off);
        if (ov < bv || (ov == bv && oi < bi)) { bv = ov; bi = oi; }
    }
    // (bv, bi) uniform across the warp: gather + output + loss partial
    {
        const float* er = g_embT + (size_t)bi * DIM;
        float4 qa = *(const float4*)&er[lane * 8];
        float4 qb = *(const float4*)&er[lane * 8 + 4];
        float4 xa = *(const float4*)&xr[lane * 8];
        float4 xb = *(const float4*)&xr[lane * 8 + 4];
        *(float4*)&out[(size_t)gw * DIM + lane * 8] = qa;
        *(float4*)&out[(size_t)gw * DIM + lane * 8 + 4] = qb;
        float d0 = qa.x - xa.x, d1 = qa.y - xa.y, d2 = qa.z - xa.z, d3 = qa.w - xa.w;
        float d4 = qb.x - xb.x, d5 = qb.y - xb.y, d6 = qb.z - xb.z, d7 = qb.w - xb.w;
        double ls = (double)(d0 * d0) + (double)(d1 * d1)
                  + (double)(d2 * d2) + (double)(d3 * d3)
                  + (double)(d4 * d4) + (double)(d5 * d5)
                  + (double)(d6 * d6) + (double)(d7 * d7);
        #pragma unroll
        for (int off = 16; off > 0; off >>= 1)
            ls += __shfl_xor_sync(0xFFFFFFFFu, ls, off);
        if (lane == 0) g_partial[gw] = ls;
    }
}

// ======================= finalize: loss scalar =============================
__global__ __launch_bounds__(1024) void finalize_kernel(float* __restrict__ out, int lossPos) {
    __shared__ double sred[1024];
    int t = threadIdx.x;
    double s = 0.0;
    for (int i = t; i < N_ROWS; i += 1024) s += g_partial[i];
    sred[t] = s;
    __syncthreads();
    #pragma unroll
    for (int off = 512; off > 0; off >>= 1) {
        if (t < off) sred[t] += sred[t + off];
        __syncthreads();
    }
    if (t == 0) {
        float m = (float)(sred[0] / (double)((size_t)N_ROWS * DIM));
        out[lossPos] = m + 0.25f * m;
    }
}

// ===========================================================================
extern "C" void kernel_launch(void* const* d_in, const int* in_sizes, int n_in,
                              void* d_out, int out_size) {
    const float* X = (const float*)d_in[0];   // inputs   [64,512,256]
    const float* E = (const float*)d_in[1];   // embeddings [256,8192]
    float* out = (float*)d_out;

    cudaFuncSetAttribute(phase1_kernel,
                         cudaFuncAttributeMaxDynamicSharedMemorySize, SMEM_P1);

    prep_kernel<<<PREP_GRID, 256>>>(X, E);
    phase1_kernel<<<P1GRID, 512, SMEM_P1>>>();
    rescore_gather_kernel<<<N_ROWS / 8, 256>>>(X, out);
    finalize_kernel<<<1, 1024>>>(out, out_size - 1);
}

// round 17
// speedup vs baseline: 1.1791x; 1.1791x over previous
#include <cuda_runtime.h>
#include <cuda_bf16.h>
#include <math.h>
#include <stdint.h>

#define N_ROWS 32768
#define DIM    256
#define KCODES 8192

#define BM      128
#define BNH     128                  // per-half k-tile width
#define HTILES  (KCODES / BNH / 2)   // 32 tiles per half
#define STAGESH (HTILES * 2)         // 64 pipeline stages per half (tile x dchunk)
#define CAND_MAX 64
#define MARGIN  0.125f

// ---- scratch (device globals; no runtime allocation) ----
__device__ float  g_xnorm[N_ROWS];
__device__ float  g_enorm[KCODES];
__device__ float  g_embT[KCODES * DIM];                 // [K][D] fp32 for gather/rescore
__device__ __nv_bfloat16 g_Eh[KCODES * DIM];            // [K][D] bf16
__device__ __nv_bfloat16 g_Xh[(size_t)N_ROWS * DIM];    // [N][D] bf16
__device__ int    g_cand[(size_t)N_ROWS * CAND_MAX];
__device__ int    g_candCnt[N_ROWS];
__device__ double g_partial[N_ROWS];                    // one partial per row (1 warp/row)

// =========================== helpers ===================================
__device__ __forceinline__ uint32_t s2u(const void* p) {
    uint32_t a;
    asm("{ .reg .u64 t; cvta.to.shared.u64 t, %1; cvt.u32.u64 %0, t; }" : "=r"(a) : "l"(p));
    return a;
}
__device__ __forceinline__ unsigned fenc(float f) {
    unsigned b = __float_as_uint(f);
    return (b & 0x80000000u) ? ~b : (b | 0x80000000u);
}
__device__ __forceinline__ float fdec(unsigned u) {
    return (u & 0x80000000u) ? __uint_as_float(u & 0x7FFFFFFFu) : __uint_as_float(~u);
}
__device__ __forceinline__ void ldsm4(uint32_t* d, uint32_t addr) {
    asm volatile("ldmatrix.sync.aligned.m8n8.x4.shared.b16 {%0,%1,%2,%3}, [%4];"
        : "=r"(d[0]), "=r"(d[1]), "=r"(d[2]), "=r"(d[3]) : "r"(addr));
}
__device__ __forceinline__ void mma_bf16(float* c, const uint32_t* a, const uint32_t* b) {
    asm volatile("mma.sync.aligned.m16n8k16.row.col.f32.bf16.bf16.f32 "
        "{%0,%1,%2,%3}, {%4,%5,%6,%7}, {%8,%9}, {%0,%1,%2,%3};"
        : "+f"(c[0]), "+f"(c[1]), "+f"(c[2]), "+f"(c[3])
        : "r"(a[0]), "r"(a[1]), "r"(a[2]), "r"(a[3]), "r"(b[0]), "r"(b[1]));
}
__device__ __forceinline__ void cpa16(uint32_t dst, const void* src) {
    asm volatile("cp.async.cg.shared.global [%0], [%1], 16;" :: "r"(dst), "l"(src));
}
#define CP_COMMIT() asm volatile("cp.async.commit_group;" ::: "memory")
#define CP_WAIT0()  asm volatile("cp.async.wait_group 0;" ::: "memory")
#define HBAR(h)     asm volatile("bar.sync %0, %1;" :: "r"(1 + (h)), "r"(256) : "memory")

// ======================= fused prep kernel ================================
// blockIdx.x ranges: [0,32) enorm | [32,2080) prepE | [2080,6176) prepX
#define PREP_ENORM 32
#define PREP_E     2048
#define PREP_X     4096
#define PREP_GRID  (PREP_ENORM + PREP_E + PREP_X)

__global__ __launch_bounds__(256) void prep_kernel(const float* __restrict__ X,
                                                   const float* __restrict__ E) {
    int b = blockIdx.x;
    if (b < PREP_ENORM) {
        // ---- enorm: sequential d loop per code (R3/R5 numerics) ----
        int k = b * 256 + threadIdx.x;
        float s = 0.0f;
        #pragma unroll 8
        for (int d = 0; d < DIM; d++) { float v = E[(size_t)d * KCODES + k]; s += v * v; }
        g_enorm[k] = s;
    } else if (b < PREP_ENORM + PREP_E) {
        // ---- prepE: E [D][K] -> embT fp32 [K][D] + Eh bf16 [K][D] ----
        __shared__ float tile[32][33];
        int idx = b - PREP_ENORM;
        int kBase = (idx & 255) * 32, dBase = (idx >> 8) * 32;
        int tx = threadIdx.x & 31, ty = threadIdx.x >> 5;   // (32, 8)
        #pragma unroll
        for (int i = 0; i < 32; i += 8)
            tile[ty + i][tx] = E[(size_t)(dBase + ty + i) * KCODES + kBase + tx];
        __syncthreads();
        #pragma unroll
        for (int i = 0; i < 32; i += 8) {
            float v = tile[tx][ty + i];
            size_t o = (size_t)(kBase + ty + i) * DIM + dBase + tx;
            g_embT[o] = v;
            g_Eh[o] = __float2bfloat16(v);
        }
    } else {
        // ---- prepX: per-row ||x||^2 + bf16 convert (R5 numerics) ----
        int idx = b - (PREP_ENORM + PREP_E);
        int gwarp = (idx * 256 + threadIdx.x) >> 5;
        int lane = threadIdx.x & 31;
        const float* xr = X + (size_t)gwarp * DIM;
        float4 a = *(const float4*)&xr[lane * 8];
        float4 bb = *(const float4*)&xr[lane * 8 + 4];
        float s = a.x * a.x + a.y * a.y + a.z * a.z + a.w * a.w;
        s += bb.x * bb.x + bb.y * bb.y + bb.z * bb.z + bb.w * bb.w;
        #pragma unroll
        for (int off = 16; off > 0; off >>= 1) s += __shfl_xor_sync(0xFFFFFFFFu, s, off);
        if (lane == 0) g_xnorm[gwarp] = s;
        __nv_bfloat162 p0 = make_bfloat162(__float2bfloat16(a.x), __float2bfloat16(a.y));
        __nv_bfloat162 p1 = make_bfloat162(__float2bfloat16(a.z), __float2bfloat16(a.w));
        __nv_bfloat162 p2 = make_bfloat162(__float2bfloat16(bb.x), __float2bfloat16(bb.y));
        __nv_bfloat162 p3 = make_bfloat162(__float2bfloat16(bb.z), __float2bfloat16(bb.w));
        uint4 v = make_uint4(*(uint32_t*)&p0, *(uint32_t*)&p1, *(uint32_t*)&p2, *(uint32_t*)&p3);
        *(uint4*)&g_Xh[(size_t)gwarp * DIM + lane * 8] = v;
    }
}

// ======== phase 1: bf16 HMMA, two desynced halves, 32x64 warp tiles ========
// smem: A 64KB | B[half][buf] 4x32KB | rowMinKey[128] | rowCnt[128]
#define SMEM_BBASE 65536
#define BUFOFF(h, b) (SMEM_BBASE + ((h) * 2 + (b)) * 32768)
#define SMEM_KEY 196608
#define SMEM_CNT 197120
#define SMEM_P1  197632

__global__ __launch_bounds__(512, 1) void phase1_kernel() {
    extern __shared__ char smem[];
    uint32_t sb = s2u(smem);
    unsigned* rowMinKey = (unsigned*)(smem + SMEM_KEY);
    int*      rowCnt    = (int*)(smem + SMEM_CNT);

    int tid = threadIdx.x, lane = tid & 31, wid = tid >> 5;
    int half = wid >> 3;
    int wh = wid & 7, wm = wh >> 1, wn = wh & 1;
    int g = lane >> 2, q = lane & 3;
    int htid = tid & 255;
    int rowBase = blockIdx.x * BM;

    if (tid < BM) { rowMinKey[tid] = 0xFFFFFFFFu; rowCnt[tid] = 0; }

    int rA = wm * 32 + (lane & 7) + ((lane >> 3) & 1) * 8;
    int caBit = lane >> 4;
    int rB = wn * 64 + (lane & 7) + ((lane >> 4) & 1) * 8;
    int cbBit = (lane >> 3) & 1;
    uint32_t aRowBase = sb + rA * 512;

    // hoisted prefetch addressing (c, gs invariant across unrolled i)
    int pAc = tid & 31, pAr = tid >> 5;               // A copy: 32 chunks/row
    int pAgs = (pAc & ~7) | ((pAc ^ pAr) & 7);
    uint32_t pAdst = sb + pAr * 512 + pAgs * 16;      // + i*8192
    uint32_t pAsrc = (uint32_t)pAr * 512 + pAc * 16;  // + i*8192
    int pBc = htid & 15, pBr = htid >> 4;             // B copy: 16 chunks/row
    int pBgs = (pBc & ~7) | ((pBc ^ pBr) & 7);
    uint32_t pBdstOff = (uint32_t)pBr * 256 + pBgs * 16;   // + i*4096
    uint32_t pBsrcOff = (uint32_t)pBr * 512 + pBc * 16;    // + i*8192

    {
        const char* srcA = (const char*)g_Xh + (size_t)rowBase * 512 + pAsrc;
        #pragma unroll
        for (int i = 0; i < 8; i++)
            cpa16(pAdst + i * 8192, srcA + (size_t)i * 8192);
        const char* srcB = (const char*)g_Eh + (size_t)(half * BNH) * 512 + pBsrcOff;
        uint32_t dstB = sb + BUFOFF(half, 0) + pBdstOff;
        #pragma unroll
        for (int i = 0; i < 8; i++)
            cpa16(dstB + i * 4096, srcB + (size_t)i * 8192);
        CP_COMMIT();
        CP_WAIT0();
    }
    __syncthreads();

    float acc[2][8][4];
    int buf = 0;
    for (int s = 0; s < STAGESH; s++) {
        int t = s >> 1, dc = s & 1;
        int kbase = (2 * t + half) * BNH;

        if (s + 1 < STAGESH) {
            int t2 = (s + 1) >> 1, dc2 = (s + 1) & 1;
            const char* srcB = (const char*)g_Eh
                + (size_t)((2 * t2 + half) * BNH) * 512 + dc2 * 256 + pBsrcOff;
            uint32_t dstB = sb + BUFOFF(half, buf ^ 1) + pBdstOff;
            #pragma unroll
            for (int i = 0; i < 8; i++)
                cpa16(dstB + i * 4096, srcB + (size_t)i * 8192);
            CP_COMMIT();
        }

        if (dc == 0) {
            #pragma unroll
            for (int mt = 0; mt < 2; mt++)
                #pragma unroll
                for (int nt = 0; nt < 8; nt++)
                    #pragma unroll
                    for (int e = 0; e < 4; e++) acc[mt][nt][e] = 0.0f;
        }
        float en[8][2];
        if (dc == 1) {
            #pragma unroll
            for (int nt = 0; nt < 8; nt++)
                #pragma unroll
                for (int e = 0; e < 2; e++)
                    en[nt][e] = __ldg(&g_enorm[kbase + wn * 64 + nt * 8 + q * 2 + e]);
        }

        uint32_t bChunk = sb + BUFOFF(half, buf) + rB * 256;
        #pragma unroll
        for (int ks = 0; ks < 8; ks++) {
            uint32_t af0[4], af1[4], bf[4][4];
            int ksg = dc * 8 + ks;
            int cA = ksg * 2 + caBit;
            int gsA = (cA & ~7) | ((cA ^ rA) & 7);
            uint32_t aAddr = aRowBase + gsA * 16;
            ldsm4(af0, aAddr);
            ldsm4(af1, aAddr + 16 * 512);
            int cB = ks * 2 + cbBit;
            int gsB = (cB & ~7) | ((cB ^ rB) & 7);
            uint32_t bAddr = bChunk + gsB * 16;
            ldsm4(bf[0], bAddr);
            ldsm4(bf[1], bAddr + 16 * 256);
            ldsm4(bf[2], bAddr + 32 * 256);
            ldsm4(bf[3], bAddr + 48 * 256);
            #pragma unroll
            for (int nt = 0; nt < 8; nt++) {
                mma_bf16(acc[0][nt], af0, bf[nt >> 1] + 2 * (nt & 1));
                mma_bf16(acc[1][nt], af1, bf[nt >> 1] + 2 * (nt & 1));
            }
        }

        if (dc == 1) {
            if (t == 0) {
                #pragma unroll
                for (int mt = 0; mt < 2; mt++)
                    #pragma unroll
                    for (int h2 = 0; h2 < 2; h2++) {
                        int rl = wm * 32 + mt * 16 + g + h2 * 8;
                        float tm = INFINITY;
                        #pragma unroll
                        for (int nt = 0; nt < 8; nt++)
                            #pragma unroll
                            for (int e = 0; e < 2; e++)
                                tm = fminf(tm, fmaf(-2.0f, acc[mt][nt][h2 * 2 + e], en[nt][e]));
                        atomicMin(&rowMinKey[rl], fenc(tm));
                    }
                HBAR(half);
            }
            #pragma unroll
            for (int mt = 0; mt < 2; mt++) {
                #pragma unroll
                for (int h2 = 0; h2 < 2; h2++) {
                    int rl = wm * 32 + mt * 16 + g + h2 * 8;
                    unsigned curKey = rowMinKey[rl];       // stale >= final min: safe
                    float thr = fdec(curKey) + MARGIN;
                    float tm = INFINITY;
                    #pragma unroll
                    for (int nt = 0; nt < 8; nt++)
                        #pragma unroll
                        for (int e = 0; e < 2; e++) {
                            float d = fmaf(-2.0f, acc[mt][nt][h2 * 2 + e], en[nt][e]);
                            tm = fminf(tm, d);
                            if (d < thr) {
                                int pos = atomicAdd(&rowCnt[rl], 1);
                                if (pos < CAND_MAX)
                                    g_cand[(size_t)(rowBase + rl) * CAND_MAX + pos] =
                                        kbase + wn * 64 + nt * 8 + q * 2 + e;
                            }
                        }
                    if (fenc(tm) < curKey) atomicMin(&rowMinKey[rl], fenc(tm));
                }
            }
        }

        CP_WAIT0();
        HBAR(half);
        buf ^= 1;
    }

    __syncthreads();
    if (tid < BM) g_candCnt[rowBase + tid] = rowCnt[tid];
}

// ===== phase 2: exact fp32 rescore + fused gather/output/loss-partial ======
__global__ __launch_bounds__(256) void rescore_gather_kernel(const float* __restrict__ X,
                                                             float* __restrict__ out) {
    int gw = (blockIdx.x * blockDim.x + threadIdx.x) >> 5;   // one warp per row
    int lane = threadIdx.x & 31;
    const float* xr = X + (size_t)gw * DIM;
    float xn = g_xnorm[gw];
    int cnt = g_candCnt[gw];
    float bv = INFINITY;
    int   bi = 0x7FFFFFFF;

    if (cnt <= CAND_MAX) {
        float4 xa = *(const float4*)&xr[lane * 8];
        float4 xb = *(const float4*)&xr[lane * 8 + 4];
        for (int ci = 0; ci < cnt; ci++) {
            int k = g_cand[(size_t)gw * CAND_MAX + ci];
            const float* er = g_embT + (size_t)k * DIM;
            float4 ea = *(const float4*)&er[lane * 8];
            float4 eb = *(const float4*)&er[lane * 8 + 4];
            float d = xa.x * ea.x + xa.y * ea.y + xa.z * ea.z + xa.w * ea.w
                    + xb.x * eb.x + xb.y * eb.y + xb.z * eb.z + xb.w * eb.w;
            #pragma unroll
            for (int off = 16; off > 0; off >>= 1) d += __shfl_xor_sync(0xFFFFFFFFu, d, off);
            float dist = fmaf(-2.0f, d, xn) + g_enorm[k];
            if (dist < bv || (dist == bv && k < bi)) { bv = dist; bi = k; }
        }
    } else {
        // rare overflow: full exact scan
        for (int k = lane; k < KCODES; k += 32) {
            const float* er = g_embT + (size_t)k * DIM;
            float d = 0.0f;
            #pragma unroll 8
            for (int j = 0; j < DIM; j += 4) {
                float4 e4 = *(const float4*)&er[j];
                float4 x4 = *(const float4*)&xr[j];
                d += x4.x * e4.x + x4.y * e4.y + x4.z * e4.z + x4.w * e4.w;
            }
            float dist = fmaf(-2.0f, d, xn) + g_enorm[k];
            if (dist < bv || (dist == bv && k < bi)) { bv = dist; bi = k; }
        }
    }
    #pragma unroll
    for (int off = 16; off > 0; off >>= 1) {
        float ov = __shfl_xor_sync(0xFFFFFFFFu, bv, off);
        int   oi = __shfl_xor_sync(0xFFFFFFFFu, bi, off);
        if (ov < bv || (ov == bv && oi < bi)) { bv = ov; bi = oi; }
    }
    // (bv, bi) uniform across the warp: gather + output + loss partial
    {
        const float* er = g_embT + (size_t)bi * DIM;
        float4 qa = *(const float4*)&er[lane * 8];
        float4 qb = *(const float4*)&er[lane * 8 + 4];
        float4 xa = *(const float4*)&xr[lane * 8];
        float4 xb = *(const float4*)&xr[lane * 8 + 4];
        *(float4*)&out[(size_t)gw * DIM + lane * 8] = qa;
        *(float4*)&out[(size_t)gw * DIM + lane * 8 + 4] = qb;
        float d0 = qa.x - xa.x, d1 = qa.y - xa.y, d2 = qa.z - xa.z, d3 = qa.w - xa.w;
        float d4 = qb.x - xb.x, d5 = qb.y - xb.y, d6 = qb.z - xb.z, d7 = qb.w - xb.w;
        double ls = (double)(d0 * d0) + (double)(d1 * d1)
                  + (double)(d2 * d2) + (double)(d3 * d3)
                  + (double)(d4 * d4) + (double)(d5 * d5)
                  + (double)(d6 * d6) + (double)(d7 * d7);
        #pragma unroll
        for (int off = 16; off > 0; off >>= 1)
            ls += __shfl_xor_sync(0xFFFFFFFFu, ls, off);
        if (lane == 0) g_partial[gw] = ls;
    }
}

// ======================= finalize: loss scalar =============================
__global__ __launch_bounds__(1024) void finalize_kernel(float* __restrict__ out, int lossPos) {
    __shared__ double sred[1024];
    int t = threadIdx.x;
    // 4 independent accumulators break the serial add chain (fixed order)
    double s0 = 0.0, s1 = 0.0, s2 = 0.0, s3 = 0.0;
    #pragma unroll 2
    for (int i = t * 4; i < N_ROWS; i += 1024 * 4) {
        s0 += g_partial[i];
        s1 += g_partial[i + 1];
        s2 += g_partial[i + 2];
        s3 += g_partial[i + 3];
    }
    sred[t] = (s0 + s1) + (s2 + s3);
    __syncthreads();
    #pragma unroll
    for (int off = 512; off > 0; off >>= 1) {
        if (t < off) sred[t] += sred[t + off];
        __syncthreads();
    }
    if (t == 0) {
        float m = (float)(sred[0] / (double)((size_t)N_ROWS * DIM));
        out[lossPos] = m + 0.25f * m;
    }
}

// ===========================================================================
extern "C" void kernel_launch(void* const* d_in, const int* in_sizes, int n_in,
                              void* d_out, int out_size) {
    const float* X = (const float*)d_in[0];   // inputs   [64,512,256]
    const float* E = (const float*)d_in[1];   // embeddings [256,8192]
    float* out = (float*)d_out;

    cudaFuncSetAttribute(phase1_kernel,
                         cudaFuncAttributeMaxDynamicSharedMemorySize, SMEM_P1);

    prep_kernel<<<PREP_GRID, 256>>>(X, E);
    phase1_kernel<<<N_ROWS / BM, 512, SMEM_P1>>>();
    rescore_gather_kernel<<<N_ROWS / 8, 256>>>(X, out);
    finalize_kernel<<<1, 1024>>>(out, out_size - 1);
}